// round 12
// baseline (speedup 1.0000x reference)
#include <cuda_runtime.h>
#include <math.h>

#define HH 512
#define WW 512
#define NG 10000
#define NVIEWS 4
#define PATCH_HALF 20   // off = -20 .. 19
#define TPG 4           // threads (rows) cooperating per (view, gaussian)
#define GPW 8           // gaussians per warp (32 / TPG)
#define NWORK (NVIEWS * NG)
#define WARPS_PER_VIEW (NG / GPW)          // 1250, exact
#define NBLK (NWORK / (GPW * 8))           // 625 blocks of 8 warps, exact

__global__ void __launch_bounds__(256) fused_kernel(
    const float* __restrict__ poses,      // (4,4,4)
    const float* __restrict__ K,          // (3,3)
    const float* __restrict__ means,      // (N,3)
    const float* __restrict__ log_scales, // (N,3)
    const float4* __restrict__ quats,     // (N,4) - 16B aligned
    const float* __restrict__ shs,        // (N,3,16)
    const float* __restrict__ opac,       // (N,1)
    float* __restrict__ out)              // (4,512,512,3)
{
    int gtid  = blockIdx.x * blockDim.x + threadIdx.x;
    int warp  = gtid >> 5;                 // global warp id
    int lane  = threadIdx.x & 31;

    // NG % GPW == 0 -> whole warp maps to ONE view (uniform across lanes)
    int view   = warp / WARPS_PER_VIEW;    // 0..3, constant-mul division
    int base_n = warp * GPW - view * NG;   // first gaussian index for this warp
    float* img = out + (size_t)view * HH * WW * 3;

    // per-lane setup results (valid in lanes 0..GPW-1)
    float r_uvx = 0.f, r_uvy = 0.f, r_iA = 0.f, r_iB = 0.f, r_iC = 0.f;
    float r_w0 = 0.f, r_w1 = 0.f, r_w2 = 0.f;
    int   r_xy = 0, r_nxny = 0;            // nxny = nx | ny<<8 (ny=0 default)

    if (lane < GPW) {
        int n = base_n + lane;

        float mx = means[n * 3 + 0];
        float my = means[n * 3 + 1];
        float mz = means[n * 3 + 2];

        const float* P = poses + view * 16;
        float pcx = P[0] * mx + P[1] * my + P[2]  * mz + P[3];
        float pcy = P[4] * mx + P[5] * my + P[6]  * mz + P[7];
        float pcz = P[8] * mx + P[9] * my + P[10] * mz + P[11];

        bool ok = (pcz >= 0.1f);

        float ppx = K[0] * pcx + K[1] * pcy + K[2] * pcz;
        float ppy = K[3] * pcx + K[4] * pcy + K[5] * pcz;
        float ppz = K[6] * pcx + K[7] * pcy + K[8] * pcz;

        float zd  = ppz + 1e-8f;
        float uvx = fdividef(ppx, zd);
        float uvy = fdividef(ppy, zd);

        ok = ok && (uvx > -1.f && uvx < (float)WW && uvy > -1.f && uvy < (float)HH);

        if (ok) {
            int u = (int)uvx;   // trunc; in [0,511]
            int v = (int)uvy;

            float s0 = __expf(log_scales[n * 3 + 0]);
            float s1 = __expf(log_scales[n * 3 + 1]);
            float s2 = __expf(log_scales[n * 3 + 2]);

            float4 qv = quats[n];
            float qw = qv.x, qx = qv.y, qy = qv.z, qz = qv.w;

            float R00 = 1.f - 2.f * (qy * qy + qz * qz);
            float R01 = 2.f * (qx * qy - qw * qz);
            float R02 = 2.f * (qx * qz + qw * qy);
            float R10 = 2.f * (qx * qy + qw * qz);
            float R11 = 1.f - 2.f * (qx * qx + qz * qz);
            float R12 = 2.f * (qy * qz - qw * qx);

            float a = s0 * R00 * R00 + s1 * R01 * R01 + s2 * R02 * R02;
            float b = s0 * R00 * R10 + s1 * R01 * R11 + s2 * R02 * R12;
            float d = s0 * R10 * R10 + s1 * R11 * R11 + s2 * R12 * R12;
            float det = a * d - b * b;
            float invdet = fdividef(1.f, det);
            float iA = d * invdet;
            float iB = -b * invdet;
            float iC = a * invdet;

            float op = fdividef(1.f, 1.f + __expf(-opac[n]));
            float w0 = fdividef(op, 1.f + __expf(-shs[n * 48 + 0 * 16]));
            float w1 = fdividef(op, 1.f + __expf(-shs[n * 48 + 1 * 16]));
            float w2 = fdividef(op, 1.f + __expf(-shs[n * 48 + 2 * 16]));

            // conservative ellipse bbox; exact q<2ln(1000) test reapplied per pixel
            const float QM = 14.2f;
            float rx = sqrtf(QM * a);
            float ry = sqrtf(QM * d);

            float fracx = uvx - (float)u;
            float fracy = uvy - (float)v;

            int ox_lo = (int)ceilf(fracx - rx);
            int ox_hi = (int)floorf(fracx + rx);
            int oy_lo = (int)ceilf(fracy - ry);
            int oy_hi = (int)floorf(fracy + ry);

            ox_lo = max(ox_lo, max(-PATCH_HALF, -u));
            ox_hi = min(ox_hi, min(PATCH_HALF - 1, WW - 1 - u));
            oy_lo = max(oy_lo, max(-PATCH_HALF, -v));
            oy_hi = min(oy_hi, min(PATCH_HALF - 1, HH - 1 - v));

            int nx = ox_hi - ox_lo + 1;
            int ny = oy_hi - oy_lo + 1;
            if (nx > 0 && ny > 0) {
                r_uvx = uvx; r_uvy = uvy;
                r_iA = iA; r_iB = iB; r_iC = iC;
                r_w0 = w0; r_w1 = w1; r_w2 = w2;
                r_xy = (u + ox_lo) | ((v + oy_lo) << 16);
                r_nxny = nx | (ny << 8);     // nx,ny <= 40
            }
        }
    }

    // broadcast records: lane l splats gaussian (l>>2), held by source lane (l>>2)
    int src = lane >> 2;           // 0..7
    const unsigned FULL = 0xFFFFFFFFu;
    int   nxny   = __shfl_sync(FULL, r_nxny, src);
    float uvx    = __shfl_sync(FULL, r_uvx, src);
    float uvy    = __shfl_sync(FULL, r_uvy, src);
    float iA     = __shfl_sync(FULL, r_iA, src);
    float iB     = __shfl_sync(FULL, r_iB, src);
    float iC     = __shfl_sync(FULL, r_iC, src);
    float w0     = __shfl_sync(FULL, r_w0, src);
    float w1     = __shfl_sync(FULL, r_w1, src);
    float w2     = __shfl_sync(FULL, r_w2, src);
    int   xy0    = __shfl_sync(FULL, r_xy, src);

    int nx = nxny & 0xFF;
    int ny = nxny >> 8;

    int sub = lane & (TPG - 1);
    if (sub >= ny) return;

    int x0 = xy0 & 0xFFFF;
    int y0 = xy0 >> 16;
    float px0  = (float)x0 - uvx;
    float iB2  = 2.f * iB;

    // each lane takes rows sub, sub+TPG, ...; forward-difference along x
    for (int r = sub; r < ny; r += TPG) {
        int yy = y0 + r;
        float py = (float)yy - uvy;
        float c1 = iB2 * py;           // linear px coefficient
        float c0 = iC * py * py;       // constant term
        float px = px0;
        float* pix = img + ((size_t)yy * WW + x0) * 3;
        for (int i = 0; i < nx; ++i, px += 1.f, pix += 3) {
            float q = (iA * px + c1) * px + c0;
            // g > 0.001  <=>  q < 2*ln(1000). Inside: expo in (-6.91, 0] so the
            // reference clamps to [-10, 0] are identity.
            if (q < 13.815511f) {
                float gg = __expf(-0.5f * q);
                atomicAdd(pix + 0, gg * w0);
                atomicAdd(pix + 1, gg * w1);
                atomicAdd(pix + 2, gg * w2);
            }
        }
    }
}

extern "C" void kernel_launch(void* const* d_in, const int* in_sizes, int n_in,
                              void* d_out, int out_size) {
    const float* poses      = (const float*)d_in[0];
    const float* intr       = (const float*)d_in[1];
    const float* means      = (const float*)d_in[2];
    const float* log_scales = (const float*)d_in[3];
    const float4* quats     = (const float4*)d_in[4];
    const float* shs        = (const float*)d_in[5];
    const float* opac       = (const float*)d_in[6];
    float* out = (float*)d_out;

    // zero via driver memset node (graph-capturable, no alloc)
    cudaMemsetAsync(out, 0, (size_t)out_size * sizeof(float), 0);

    fused_kernel<<<NBLK, 256>>>(poses, intr, means, log_scales, quats, shs, opac, out);
}

// round 13
// speedup vs baseline: 1.2937x; 1.2937x over previous
#include <cuda_runtime.h>
#include <math.h>

#define HH 512
#define WW 512
#define NG 10000
#define NVIEWS 4
#define PATCH_HALF 20   // off = -20 .. 19
#define TPG 4           // threads cooperating per (view, gaussian)
#define GPW 8           // gaussians per warp (32 / TPG)
#define NWORK (NVIEWS * NG)
#define WARPS_PER_VIEW (NG / GPW)          // 1250, exact
#define NBLK (NWORK / (GPW * 8))           // 625 blocks of 8 warps, exact
#define NOUT4 (NVIEWS * HH * WW * 3 / 4)   // 786432 float4s

// grid-barrier state; all return to 0 after every run (self-resetting)
__device__ int g_arrive = 0;
__device__ int g_flag   = 0;
__device__ int g_done   = 0;

__global__ void __launch_bounds__(256) fused_kernel(
    const float* __restrict__ poses,      // (4,4,4)
    const float* __restrict__ K,          // (3,3)
    const float* __restrict__ means,      // (N,3)
    const float* __restrict__ log_scales, // (N,3)
    const float4* __restrict__ quats,     // (N,4) - 16B aligned
    const float* __restrict__ shs,        // (N,3,16)
    const float* __restrict__ opac,       // (N,1)
    float* __restrict__ out)              // (4,512,512,3)
{
    int gtid  = blockIdx.x * blockDim.x + threadIdx.x;
    int warp  = gtid >> 5;                 // global warp id
    int lane  = threadIdx.x & 31;

    // ---------- phase 1: zero the output (stores drain in background) --------
    {
        float4* out4 = (float4*)out;
        const int nth = NBLK * 256;
        for (int i = gtid; i < NOUT4; i += nth)
            out4[i] = make_float4(0.f, 0.f, 0.f, 0.f);
    }

    // NG % GPW == 0 -> whole warp maps to ONE view (uniform across lanes)
    int view   = warp / WARPS_PER_VIEW;    // 0..3, constant-mul division
    int base_n = warp * GPW - view * NG;   // first gaussian index for this warp
    float* img = out + (size_t)view * HH * WW * 3;

    // ---------- phase 2: setup (lanes 0..GPW-1); overlaps others' zeroing -----
    float r_uvx = 0.f, r_uvy = 0.f, r_iA = 0.f, r_iB = 0.f, r_iC = 0.f;
    float r_w0 = 0.f, r_w1 = 0.f, r_w2 = 0.f;
    int   r_xy = 0, r_nxcnt = 1, r_magic = 0;   // nxcnt = nx | cnt<<8 (cnt=0 default)

    if (lane < GPW) {
        int n = base_n + lane;

        float mx = means[n * 3 + 0];
        float my = means[n * 3 + 1];
        float mz = means[n * 3 + 2];

        const float* P = poses + view * 16;
        float pcx = P[0] * mx + P[1] * my + P[2]  * mz + P[3];
        float pcy = P[4] * mx + P[5] * my + P[6]  * mz + P[7];
        float pcz = P[8] * mx + P[9] * my + P[10] * mz + P[11];

        bool ok = (pcz >= 0.1f);

        float ppx = K[0] * pcx + K[1] * pcy + K[2] * pcz;
        float ppy = K[3] * pcx + K[4] * pcy + K[5] * pcz;
        float ppz = K[6] * pcx + K[7] * pcy + K[8] * pcz;

        float zd  = ppz + 1e-8f;
        float uvx = fdividef(ppx, zd);
        float uvy = fdividef(ppy, zd);

        ok = ok && (uvx > -1.f && uvx < (float)WW && uvy > -1.f && uvy < (float)HH);

        if (ok) {
            int u = (int)uvx;   // trunc; in [0,511]
            int v = (int)uvy;

            float s0 = __expf(log_scales[n * 3 + 0]);
            float s1 = __expf(log_scales[n * 3 + 1]);
            float s2 = __expf(log_scales[n * 3 + 2]);

            float4 qv = quats[n];
            float qw = qv.x, qx = qv.y, qy = qv.z, qz = qv.w;

            float R00 = 1.f - 2.f * (qy * qy + qz * qz);
            float R01 = 2.f * (qx * qy - qw * qz);
            float R02 = 2.f * (qx * qz + qw * qy);
            float R10 = 2.f * (qx * qy + qw * qz);
            float R11 = 1.f - 2.f * (qx * qx + qz * qz);
            float R12 = 2.f * (qy * qz - qw * qx);

            float a = s0 * R00 * R00 + s1 * R01 * R01 + s2 * R02 * R02;
            float b = s0 * R00 * R10 + s1 * R01 * R11 + s2 * R02 * R12;
            float d = s0 * R10 * R10 + s1 * R11 * R11 + s2 * R12 * R12;
            float det = a * d - b * b;
            float invdet = fdividef(1.f, det);
            float iA = d * invdet;
            float iB = -b * invdet;
            float iC = a * invdet;

            float op = fdividef(1.f, 1.f + __expf(-opac[n]));
            float w0 = fdividef(op, 1.f + __expf(-shs[n * 48 + 0 * 16]));
            float w1 = fdividef(op, 1.f + __expf(-shs[n * 48 + 1 * 16]));
            float w2 = fdividef(op, 1.f + __expf(-shs[n * 48 + 2 * 16]));

            // conservative ellipse bbox; exact q<2ln(1000) test reapplied per pixel
            const float QM = 14.2f;
            float rx = sqrtf(QM * a);
            float ry = sqrtf(QM * d);

            float fracx = uvx - (float)u;
            float fracy = uvy - (float)v;

            int ox_lo = (int)ceilf(fracx - rx);
            int ox_hi = (int)floorf(fracx + rx);
            int oy_lo = (int)ceilf(fracy - ry);
            int oy_hi = (int)floorf(fracy + ry);

            ox_lo = max(ox_lo, max(-PATCH_HALF, -u));
            ox_hi = min(ox_hi, min(PATCH_HALF - 1, WW - 1 - u));
            oy_lo = max(oy_lo, max(-PATCH_HALF, -v));
            oy_hi = min(oy_hi, min(PATCH_HALF - 1, HH - 1 - v));

            int nx = ox_hi - ox_lo + 1;
            int ny = oy_hi - oy_lo + 1;
            if (nx > 0 && ny > 0) {
                r_uvx = uvx; r_uvy = uvy;
                r_iA = iA; r_iB = iB; r_iC = iC;
                r_w0 = w0; r_w1 = w1; r_w2 = w2;
                r_xy = (u + ox_lo) | ((v + oy_lo) << 16);
                r_nxcnt = nx | ((nx * ny) << 8);   // nx<=40, cnt<=1600 fits
                r_magic = (int)(0xFFFFFFFFu / (unsigned)nx + 1u);  // exact small div
            }
        }
    }

    // broadcast records: lane l splats gaussian (l>>2), held by source lane (l>>2)
    int src = lane >> 2;           // 0..7
    const unsigned FULL = 0xFFFFFFFFu;
    int   nxcnt  = __shfl_sync(FULL, r_nxcnt, src);
    float uvx    = __shfl_sync(FULL, r_uvx, src);
    float uvy    = __shfl_sync(FULL, r_uvy, src);
    float iA     = __shfl_sync(FULL, r_iA, src);
    float iB     = __shfl_sync(FULL, r_iB, src);
    float iC     = __shfl_sync(FULL, r_iC, src);
    float w0     = __shfl_sync(FULL, r_w0, src);
    float w1     = __shfl_sync(FULL, r_w1, src);
    float w2     = __shfl_sync(FULL, r_w2, src);
    int   xy0    = __shfl_sync(FULL, r_xy, src);
    int   magic  = __shfl_sync(FULL, r_magic, src);

    // ---------- phase 3: grid barrier (all 625 blocks co-resident) -----------
    // arrival: one atomicAdd per block. release wait: VOLATILE L2 reads with
    // nanosleep backoff (round-10's atomicAdd-polling serialized at the LTS ALU).
    __threadfence();               // zero stores visible before anyone splats
    __syncthreads();
    if (threadIdx.x == 0) {
        if (atomicAdd(&g_arrive, 1) == NBLK - 1) {
            g_arrive = 0;          // all arrived; safe to reset for next replay
            __threadfence();
            atomicExch(&g_flag, 1);   // release
        } else {
            while (*(volatile int*)&g_flag == 0) __nanosleep(64);
        }
    }
    __syncthreads();

    // ---------- phase 4: splat (no early return: tid 0 must reach reset) -----
    int nx  = nxcnt & 0xFF;
    int cnt = nxcnt >> 8;
    int sub = lane & (TPG - 1);

    if (sub < cnt) {
        int x0 = xy0 & 0xFFFF;
        int y0 = xy0 >> 16;

        for (int p = sub; p < cnt; p += TPG) {
            int oyi = (int)__umulhi((unsigned)p, (unsigned)magic);   // p / nx
            int oxi = p - oyi * nx;
            int yy = y0 + oyi;
            int xx = x0 + oxi;
            float py = (float)yy - uvy;
            float px = (float)xx - uvx;
            float q = iA * px * px + 2.f * iB * px * py + iC * py * py;
            // g > 0.001 <=> q < 2*ln(1000); inside, the [-10,0] clamps are identity
            if (q < 13.815511f) {
                float gg = __expf(-0.5f * q);
                float* pix = img + ((size_t)yy * WW + xx) * 3;
                atomicAdd(pix + 0, gg * w0);
                atomicAdd(pix + 1, gg * w1);
                atomicAdd(pix + 2, gg * w2);
            }
        }
    }

    // ---------- reset barrier state for the next replay -----------------------
    if (threadIdx.x == 0) {
        if (atomicAdd(&g_done, 1) == NBLK - 1) {   // all blocks passed the wait
            g_done = 0;
            __threadfence();
            atomicExch(&g_flag, 0);
        }
    }
}

extern "C" void kernel_launch(void* const* d_in, const int* in_sizes, int n_in,
                              void* d_out, int out_size) {
    const float* poses      = (const float*)d_in[0];
    const float* intr       = (const float*)d_in[1];
    const float* means      = (const float*)d_in[2];
    const float* log_scales = (const float*)d_in[3];
    const float4* quats     = (const float4*)d_in[4];
    const float* shs        = (const float*)d_in[5];
    const float* opac       = (const float*)d_in[6];
    float* out = (float*)d_out;

    fused_kernel<<<NBLK, 256>>>(poses, intr, means, log_scales, quats, shs, opac, out);
}

// round 14
// speedup vs baseline: 1.5013x; 1.1604x over previous
#include <cuda_runtime.h>
#include <math.h>

#define HH 512
#define WW 512
#define NG 10000
#define NVIEWS 4
#define PATCH_HALF 20   // off = -20 .. 19
#define TPG 4           // threads cooperating per (view, gaussian)
#define GPW 8           // gaussians per warp (32 / TPG)
#define NWORK (NVIEWS * NG)
#define WARPS_PER_VIEW (NG / GPW)          // 1250, exact
#define NBLK (NWORK / (GPW * 8))           // 625 blocks of 8 warps, exact

__global__ void __launch_bounds__(256) zero_out_kernel(float4* __restrict__ out) {
    int i = blockIdx.x * blockDim.x + threadIdx.x;
    out[i] = make_float4(0.f, 0.f, 0.f, 0.f);   // grid sized exactly: no bound check
}

__global__ void __launch_bounds__(256) fused_kernel(
    const float* __restrict__ poses,      // (4,4,4)
    const float* __restrict__ K,          // (3,3)
    const float* __restrict__ means,      // (N,3)
    const float* __restrict__ log_scales, // (N,3)
    const float4* __restrict__ quats,     // (N,4) - 16B aligned
    const float* __restrict__ shs,        // (N,3,16)
    const float* __restrict__ opac,       // (N,1)
    float* __restrict__ out)              // (4,512,512,3)
{
    int gtid  = blockIdx.x * blockDim.x + threadIdx.x;
    int warp  = gtid >> 5;                 // global warp id
    int lane  = threadIdx.x & 31;

    // NG % GPW == 0 -> whole warp maps to ONE view (uniform across lanes)
    int view   = warp / WARPS_PER_VIEW;    // 0..3, constant-mul division
    int base_n = warp * GPW - view * NG;   // first gaussian index for this warp
    float* img = out + (size_t)view * HH * WW * 3;

    // per-lane setup results (valid in lanes 0..GPW-1)
    float r_uvx = 0.f, r_uvy = 0.f, r_iA = 0.f, r_iB = 0.f, r_iC = 0.f;
    float r_w0 = 0.f, r_w1 = 0.f, r_w2 = 0.f;
    int   r_xy = 0, r_nxcnt = 1, r_magic = 0;   // nxcnt = nx | cnt<<8 (cnt=0 default)

    if (lane < GPW) {
        int n = base_n + lane;

        float mx = means[n * 3 + 0];
        float my = means[n * 3 + 1];
        float mz = means[n * 3 + 2];

        const float* P = poses + view * 16;
        float pcx = P[0] * mx + P[1] * my + P[2]  * mz + P[3];
        float pcy = P[4] * mx + P[5] * my + P[6]  * mz + P[7];
        float pcz = P[8] * mx + P[9] * my + P[10] * mz + P[11];

        bool ok = (pcz >= 0.1f);

        float ppx = K[0] * pcx + K[1] * pcy + K[2] * pcz;
        float ppy = K[3] * pcx + K[4] * pcy + K[5] * pcz;
        float ppz = K[6] * pcx + K[7] * pcy + K[8] * pcz;

        float zd  = ppz + 1e-8f;
        float uvx = fdividef(ppx, zd);
        float uvy = fdividef(ppy, zd);

        ok = ok && (uvx > -1.f && uvx < (float)WW && uvy > -1.f && uvy < (float)HH);

        if (ok) {
            int u = (int)uvx;   // trunc; in [0,511]
            int v = (int)uvy;

            float s0 = __expf(log_scales[n * 3 + 0]);
            float s1 = __expf(log_scales[n * 3 + 1]);
            float s2 = __expf(log_scales[n * 3 + 2]);

            float4 qv = quats[n];
            float qw = qv.x, qx = qv.y, qy = qv.z, qz = qv.w;

            float R00 = 1.f - 2.f * (qy * qy + qz * qz);
            float R01 = 2.f * (qx * qy - qw * qz);
            float R02 = 2.f * (qx * qz + qw * qy);
            float R10 = 2.f * (qx * qy + qw * qz);
            float R11 = 1.f - 2.f * (qx * qx + qz * qz);
            float R12 = 2.f * (qy * qz - qw * qx);

            float a = s0 * R00 * R00 + s1 * R01 * R01 + s2 * R02 * R02;
            float b = s0 * R00 * R10 + s1 * R01 * R11 + s2 * R02 * R12;
            float d = s0 * R10 * R10 + s1 * R11 * R11 + s2 * R12 * R12;
            float det = a * d - b * b;
            float invdet = fdividef(1.f, det);
            float iA = d * invdet;
            float iB = -b * invdet;
            float iC = a * invdet;

            float op = fdividef(1.f, 1.f + __expf(-opac[n]));
            float w0 = fdividef(op, 1.f + __expf(-shs[n * 48 + 0 * 16]));
            float w1 = fdividef(op, 1.f + __expf(-shs[n * 48 + 1 * 16]));
            float w2 = fdividef(op, 1.f + __expf(-shs[n * 48 + 2 * 16]));

            // conservative ellipse bbox; exact q<2ln(1000) test reapplied per pixel
            const float QM = 14.2f;
            float rx = sqrtf(QM * a);
            float ry = sqrtf(QM * d);

            float fracx = uvx - (float)u;
            float fracy = uvy - (float)v;

            int ox_lo = (int)ceilf(fracx - rx);
            int ox_hi = (int)floorf(fracx + rx);
            int oy_lo = (int)ceilf(fracy - ry);
            int oy_hi = (int)floorf(fracy + ry);

            ox_lo = max(ox_lo, max(-PATCH_HALF, -u));
            ox_hi = min(ox_hi, min(PATCH_HALF - 1, WW - 1 - u));
            oy_lo = max(oy_lo, max(-PATCH_HALF, -v));
            oy_hi = min(oy_hi, min(PATCH_HALF - 1, HH - 1 - v));

            int nx = ox_hi - ox_lo + 1;
            int ny = oy_hi - oy_lo + 1;
            if (nx > 0 && ny > 0) {
                r_uvx = uvx; r_uvy = uvy;
                r_iA = iA; r_iB = iB; r_iC = iC;
                r_w0 = w0; r_w1 = w1; r_w2 = w2;
                r_xy = (u + ox_lo) | ((v + oy_lo) << 16);
                r_nxcnt = nx | ((nx * ny) << 8);   // nx<=40, cnt<=1600 fits
                r_magic = (int)(0xFFFFFFFFu / (unsigned)nx + 1u);  // exact small div
            }
        }
    }

    // broadcast records: lane l splats gaussian (l>>2), held by source lane (l>>2)
    int src = lane >> 2;           // 0..7
    const unsigned FULL = 0xFFFFFFFFu;
    int   nxcnt  = __shfl_sync(FULL, r_nxcnt, src);
    float uvx    = __shfl_sync(FULL, r_uvx, src);
    float uvy    = __shfl_sync(FULL, r_uvy, src);
    float iA     = __shfl_sync(FULL, r_iA, src);
    float iB     = __shfl_sync(FULL, r_iB, src);
    float iC     = __shfl_sync(FULL, r_iC, src);
    float w0     = __shfl_sync(FULL, r_w0, src);
    float w1     = __shfl_sync(FULL, r_w1, src);
    float w2     = __shfl_sync(FULL, r_w2, src);
    int   xy0    = __shfl_sync(FULL, r_xy, src);
    int   magic  = __shfl_sync(FULL, r_magic, src);

    int nx  = nxcnt & 0xFF;
    int cnt = nxcnt >> 8;

    int sub = lane & (TPG - 1);
    if (sub >= cnt) return;

    int x0 = xy0 & 0xFFFF;
    int y0 = xy0 >> 16;

    for (int p = sub; p < cnt; p += TPG) {
        int oyi = (int)__umulhi((unsigned)p, (unsigned)magic);   // p / nx, exact
        int oxi = p - oyi * nx;
        int yy = y0 + oyi;
        int xx = x0 + oxi;
        float py = (float)yy - uvy;
        float px = (float)xx - uvx;
        float q = iA * px * px + 2.f * iB * px * py + iC * py * py;
        // g > 0.001  <=>  q < 2*ln(1000). Inside: expo in (-6.91, 0] so the
        // reference clamps to [-10, 0] are identity.
        if (q < 13.815511f) {
            float gg = __expf(-0.5f * q);
            float* pix = img + ((size_t)yy * WW + xx) * 3;
            atomicAdd(pix + 0, gg * w0);
            atomicAdd(pix + 1, gg * w1);
            atomicAdd(pix + 2, gg * w2);
        }
    }
}

extern "C" void kernel_launch(void* const* d_in, const int* in_sizes, int n_in,
                              void* d_out, int out_size) {
    const float* poses      = (const float*)d_in[0];
    const float* intr       = (const float*)d_in[1];
    const float* means      = (const float*)d_in[2];
    const float* log_scales = (const float*)d_in[3];
    const float4* quats     = (const float4*)d_in[4];
    const float* shs        = (const float*)d_in[5];
    const float* opac       = (const float*)d_in[6];
    float* out = (float*)d_out;

    int n4 = out_size / 4;                 // 786432 float4s, divisible by 256
    zero_out_kernel<<<n4 / 256, 256>>>((float4*)out);

    fused_kernel<<<NBLK, 256>>>(poses, intr, means, log_scales, quats, shs, opac, out);
}

// round 15
// speedup vs baseline: 1.5359x; 1.0231x over previous
#include <cuda_runtime.h>
#include <math.h>

#define HH 512
#define WW 512
#define NG 10000
#define NVIEWS 4
#define PATCH_HALF 20   // off = -20 .. 19
#define TPG 4           // threads cooperating per (view, gaussian)
#define GPW 8           // gaussians per warp (32 / TPG)
#define NWORK (NVIEWS * NG)
#define WARPS_PER_VIEW (NG / GPW)          // 1250, exact
#define NBLK (NWORK / (GPW * 8))           // 625 blocks of 8 warps, exact

__global__ void __launch_bounds__(256) zero_out_kernel(float4* __restrict__ out) {
    int i = blockIdx.x * blockDim.x + threadIdx.x;
    out[i] = make_float4(0.f, 0.f, 0.f, 0.f);   // grid sized exactly: no bound check
}

__global__ void __launch_bounds__(256) fused_kernel(
    const float* __restrict__ poses,      // (4,4,4)
    const float* __restrict__ K,          // (3,3)
    const float* __restrict__ means,      // (N,3)
    const float* __restrict__ log_scales, // (N,3)
    const float4* __restrict__ quats,     // (N,4) - 16B aligned
    const float* __restrict__ shs,        // (N,3,16)
    const float* __restrict__ opac,       // (N,1)
    float* __restrict__ out)              // (4,512,512,3)
{
    int gtid  = blockIdx.x * blockDim.x + threadIdx.x;
    int warp  = gtid >> 5;                 // global warp id
    int lane  = threadIdx.x & 31;

    // NG % GPW == 0 -> whole warp maps to ONE view (uniform across lanes)
    int view   = warp / WARPS_PER_VIEW;    // 0..3, constant-mul division
    int base_n = warp * GPW - view * NG;   // first gaussian index for this warp
    float* img = out + (size_t)view * HH * WW * 3;

    // ALL 32 lanes run setup; 4 lanes redundantly compute the gaussian they
    // will splat (no shuffle broadcast; predicated-off lanes would cost the
    // same warp-issue slots anyway, and 4-same-address loads broadcast in L1).
    int n = base_n + (lane >> 2);          // gaussian this lane splats
    int sub = lane & (TPG - 1);            // 0..3 within the gaussian group

    float uvx = 0.f, uvy = 0.f, iA = 0.f, iB = 0.f, iC = 0.f;
    float w0 = 0.f, w1 = 0.f, w2 = 0.f;
    int   x0 = 0, y0 = 0, nx = 1, cnt = 0;
    unsigned magic = 0;

    {
        float mx = means[n * 3 + 0];
        float my = means[n * 3 + 1];
        float mz = means[n * 3 + 2];

        const float* P = poses + view * 16;
        float pcx = P[0] * mx + P[1] * my + P[2]  * mz + P[3];
        float pcy = P[4] * mx + P[5] * my + P[6]  * mz + P[7];
        float pcz = P[8] * mx + P[9] * my + P[10] * mz + P[11];

        bool ok = (pcz >= 0.1f);

        float ppx = K[0] * pcx + K[1] * pcy + K[2] * pcz;
        float ppy = K[3] * pcx + K[4] * pcy + K[5] * pcz;
        float ppz = K[6] * pcx + K[7] * pcy + K[8] * pcz;

        float rz = fdividef(1.f, ppz + 1e-8f);   // one reciprocal, two muls
        uvx = ppx * rz;
        uvy = ppy * rz;

        ok = ok && (uvx > -1.f && uvx < (float)WW && uvy > -1.f && uvy < (float)HH);

        if (ok) {
            int u = (int)uvx;   // trunc; in [0,511]
            int v = (int)uvy;

            float s0 = __expf(log_scales[n * 3 + 0]);
            float s1 = __expf(log_scales[n * 3 + 1]);
            float s2 = __expf(log_scales[n * 3 + 2]);

            float4 qv = quats[n];
            float qw = qv.x, qx = qv.y, qy = qv.z, qz = qv.w;

            float R00 = 1.f - 2.f * (qy * qy + qz * qz);
            float R01 = 2.f * (qx * qy - qw * qz);
            float R02 = 2.f * (qx * qz + qw * qy);
            float R10 = 2.f * (qx * qy + qw * qz);
            float R11 = 1.f - 2.f * (qx * qx + qz * qz);
            float R12 = 2.f * (qy * qz - qw * qx);

            float a = s0 * R00 * R00 + s1 * R01 * R01 + s2 * R02 * R02;
            float b = s0 * R00 * R10 + s1 * R01 * R11 + s2 * R02 * R12;
            float d = s0 * R10 * R10 + s1 * R11 * R11 + s2 * R12 * R12;
            float det = a * d - b * b;
            float invdet = fdividef(1.f, det);
            iA = d * invdet;
            iB = -b * invdet;
            iC = a * invdet;

            float op = fdividef(1.f, 1.f + __expf(-opac[n]));
            w0 = fdividef(op, 1.f + __expf(-shs[n * 48 + 0 * 16]));
            w1 = fdividef(op, 1.f + __expf(-shs[n * 48 + 1 * 16]));
            w2 = fdividef(op, 1.f + __expf(-shs[n * 48 + 2 * 16]));

            // conservative ellipse bbox; exact q<2ln(1000) test reapplied per pixel
            const float QM = 14.2f;
            float rx = sqrtf(QM * a);
            float ry = sqrtf(QM * d);

            float fracx = uvx - (float)u;
            float fracy = uvy - (float)v;

            int ox_lo = (int)ceilf(fracx - rx);
            int ox_hi = (int)floorf(fracx + rx);
            int oy_lo = (int)ceilf(fracy - ry);
            int oy_hi = (int)floorf(fracy + ry);

            ox_lo = max(ox_lo, max(-PATCH_HALF, -u));
            ox_hi = min(ox_hi, min(PATCH_HALF - 1, WW - 1 - u));
            oy_lo = max(oy_lo, max(-PATCH_HALF, -v));
            oy_hi = min(oy_hi, min(PATCH_HALF - 1, HH - 1 - v));

            int nxl = ox_hi - ox_lo + 1;
            int nyl = oy_hi - oy_lo + 1;
            if (nxl > 0 && nyl > 0) {
                x0 = u + ox_lo;
                y0 = v + oy_lo;
                nx = nxl;
                cnt = nxl * nyl;
                magic = 0xFFFFFFFFu / (unsigned)nxl + 1u;  // exact div, small ints
            }
        }
    }

    if (sub >= cnt) return;

    // first iteration peeled (most lanes run exactly 1-2 iterations)
    int p = sub;
    do {
        int oyi = (int)__umulhi((unsigned)p, magic);   // p / nx, exact
        int oxi = p - oyi * nx;
        int yy = y0 + oyi;
        int xx = x0 + oxi;
        float py = (float)yy - uvy;
        float px = (float)xx - uvx;
        float q = iA * px * px + 2.f * iB * px * py + iC * py * py;
        // g > 0.001  <=>  q < 2*ln(1000). Inside: expo in (-6.91, 0] so the
        // reference clamps to [-10, 0] are identity.
        if (q < 13.815511f) {
            float gg = __expf(-0.5f * q);
            float* pix = img + ((size_t)yy * WW + xx) * 3;
            atomicAdd(pix + 0, gg * w0);
            atomicAdd(pix + 1, gg * w1);
            atomicAdd(pix + 2, gg * w2);
        }
        p += TPG;
    } while (p < cnt);
}

extern "C" void kernel_launch(void* const* d_in, const int* in_sizes, int n_in,
                              void* d_out, int out_size) {
    const float* poses      = (const float*)d_in[0];
    const float* intr       = (const float*)d_in[1];
    const float* means      = (const float*)d_in[2];
    const float* log_scales = (const float*)d_in[3];
    const float4* quats     = (const float4*)d_in[4];
    const float* shs        = (const float*)d_in[5];
    const float* opac       = (const float*)d_in[6];
    float* out = (float*)d_out;

    int n4 = out_size / 4;                 // 786432 float4s, divisible by 256
    zero_out_kernel<<<n4 / 256, 256>>>((float4*)out);

    fused_kernel<<<NBLK, 256>>>(poses, intr, means, log_scales, quats, shs, opac, out);
}

// round 16
// speedup vs baseline: 1.7881x; 1.1642x over previous
#include <cuda_runtime.h>
#include <math.h>

#define HH 512
#define WW 512
#define NG 10000
#define NVIEWS 4
#define PATCH_HALF 20   // off = -20 .. 19
#define TPG 4           // threads cooperating per (view, gaussian)
#define GPW 8           // gaussians per warp (32 / TPG)
#define NWORK (NVIEWS * NG)
#define WARPS_PER_VIEW (NG / GPW)          // 1250, exact
#define NBLK (NWORK / (GPW * 8))           // 625 blocks of 8 warps, exact
#define NOUT4 (NVIEWS * HH * WW * 3 / 4)   // 786432 float4s
#define ZBLK 1184                           // one full wave (148 SMs x 8 blocks)

__global__ void __launch_bounds__(256) zero_out_kernel(float4* __restrict__ out) {
    // signal PDL: dependent (fused) kernel may begin launching/running its
    // pre-sync phase now; memory visibility is enforced by its gridDepSync.
    cudaTriggerProgrammaticLaunchCompletion();
    int i = blockIdx.x * blockDim.x + threadIdx.x;
    const int nth = ZBLK * 256;
    for (; i < NOUT4; i += nth)
        out[i] = make_float4(0.f, 0.f, 0.f, 0.f);
}

__global__ void __launch_bounds__(256) fused_kernel(
    const float* __restrict__ poses,      // (4,4,4)
    const float* __restrict__ K,          // (3,3)
    const float* __restrict__ means,      // (N,3)
    const float* __restrict__ log_scales, // (N,3)
    const float4* __restrict__ quats,     // (N,4) - 16B aligned
    const float* __restrict__ shs,        // (N,3,16)
    const float* __restrict__ opac,       // (N,1)
    float* __restrict__ out)              // (4,512,512,3)
{
    int gtid  = blockIdx.x * blockDim.x + threadIdx.x;
    int warp  = gtid >> 5;                 // global warp id
    int lane  = threadIdx.x & 31;

    // NG % GPW == 0 -> whole warp maps to ONE view (uniform across lanes)
    int view   = warp / WARPS_PER_VIEW;    // 0..3, constant-mul division
    int base_n = warp * GPW - view * NG;   // first gaussian index for this warp
    float* img = out + (size_t)view * HH * WW * 3;

    // per-lane setup results (valid in lanes 0..GPW-1)
    float r_uvx = 0.f, r_uvy = 0.f, r_iA = 0.f, r_iB = 0.f, r_iC = 0.f;
    float r_w0 = 0.f, r_w1 = 0.f, r_w2 = 0.f;
    int   r_xy = 0, r_nxcnt = 1, r_magic = 0;   // nxcnt = nx | cnt<<8 (cnt=0 default)

    if (lane < GPW) {
        int n = base_n + lane;

        // hoist ALL per-gaussian loads (always in-bounds) so both L2 round
        // trips overlap instead of serializing across the validity check
        float mx = means[n * 3 + 0];
        float my = means[n * 3 + 1];
        float mz = means[n * 3 + 2];
        float ls0 = log_scales[n * 3 + 0];
        float ls1 = log_scales[n * 3 + 1];
        float ls2 = log_scales[n * 3 + 2];
        float4 qv = quats[n];
        float sh0 = shs[n * 48 + 0 * 16];
        float sh1 = shs[n * 48 + 1 * 16];
        float sh2 = shs[n * 48 + 2 * 16];
        float opa = opac[n];

        const float* P = poses + view * 16;
        float pcx = P[0] * mx + P[1] * my + P[2]  * mz + P[3];
        float pcy = P[4] * mx + P[5] * my + P[6]  * mz + P[7];
        float pcz = P[8] * mx + P[9] * my + P[10] * mz + P[11];

        bool ok = (pcz >= 0.1f);

        float ppx = K[0] * pcx + K[1] * pcy + K[2] * pcz;
        float ppy = K[3] * pcx + K[4] * pcy + K[5] * pcz;
        float ppz = K[6] * pcx + K[7] * pcy + K[8] * pcz;

        float rz = fdividef(1.f, ppz + 1e-8f);
        float uvx = ppx * rz;
        float uvy = ppy * rz;

        ok = ok && (uvx > -1.f && uvx < (float)WW && uvy > -1.f && uvy < (float)HH);

        if (ok) {
            int u = (int)uvx;   // trunc; in [0,511]
            int v = (int)uvy;

            float s0 = __expf(ls0);
            float s1 = __expf(ls1);
            float s2 = __expf(ls2);

            float qw = qv.x, qx = qv.y, qy = qv.z, qz = qv.w;

            float R00 = 1.f - 2.f * (qy * qy + qz * qz);
            float R01 = 2.f * (qx * qy - qw * qz);
            float R02 = 2.f * (qx * qz + qw * qy);
            float R10 = 2.f * (qx * qy + qw * qz);
            float R11 = 1.f - 2.f * (qx * qx + qz * qz);
            float R12 = 2.f * (qy * qz - qw * qx);

            float a = s0 * R00 * R00 + s1 * R01 * R01 + s2 * R02 * R02;
            float b = s0 * R00 * R10 + s1 * R01 * R11 + s2 * R02 * R12;
            float d = s0 * R10 * R10 + s1 * R11 * R11 + s2 * R12 * R12;
            float det = a * d - b * b;
            float invdet = fdividef(1.f, det);
            float iA = d * invdet;
            float iB = -b * invdet;
            float iC = a * invdet;

            float op = fdividef(1.f, 1.f + __expf(-opa));
            float w0 = fdividef(op, 1.f + __expf(-sh0));
            float w1 = fdividef(op, 1.f + __expf(-sh1));
            float w2 = fdividef(op, 1.f + __expf(-sh2));

            // conservative ellipse bbox; exact q<2ln(1000) test reapplied per pixel
            const float QM = 14.2f;
            float rx = sqrtf(QM * a);
            float ry = sqrtf(QM * d);

            float fracx = uvx - (float)u;
            float fracy = uvy - (float)v;

            int ox_lo = (int)ceilf(fracx - rx);
            int ox_hi = (int)floorf(fracx + rx);
            int oy_lo = (int)ceilf(fracy - ry);
            int oy_hi = (int)floorf(fracy + ry);

            ox_lo = max(ox_lo, max(-PATCH_HALF, -u));
            ox_hi = min(ox_hi, min(PATCH_HALF - 1, WW - 1 - u));
            oy_lo = max(oy_lo, max(-PATCH_HALF, -v));
            oy_hi = min(oy_hi, min(PATCH_HALF - 1, HH - 1 - v));

            int nx = ox_hi - ox_lo + 1;
            int ny = oy_hi - oy_lo + 1;
            if (nx > 0 && ny > 0) {
                r_uvx = uvx; r_uvy = uvy;
                r_iA = iA; r_iB = iB; r_iC = iC;
                r_w0 = w0; r_w1 = w1; r_w2 = w2;
                r_xy = (u + ox_lo) | ((v + oy_lo) << 16);
                r_nxcnt = nx | ((nx * ny) << 8);   // nx<=40, cnt<=1600 fits
                r_magic = (int)(0xFFFFFFFFu / (unsigned)nx + 1u);  // exact small div
            }
        }
    }

    // broadcast records: lane l splats gaussian (l>>2), held by source lane (l>>2)
    int src = lane >> 2;           // 0..7
    const unsigned FULL = 0xFFFFFFFFu;
    int   nxcnt  = __shfl_sync(FULL, r_nxcnt, src);
    float uvx    = __shfl_sync(FULL, r_uvx, src);
    float uvy    = __shfl_sync(FULL, r_uvy, src);
    float iA     = __shfl_sync(FULL, r_iA, src);
    float iB     = __shfl_sync(FULL, r_iB, src);
    float iC     = __shfl_sync(FULL, r_iC, src);
    float w0     = __shfl_sync(FULL, r_w0, src);
    float w1     = __shfl_sync(FULL, r_w1, src);
    float w2     = __shfl_sync(FULL, r_w2, src);
    int   xy0    = __shfl_sync(FULL, r_xy, src);
    int   magic  = __shfl_sync(FULL, r_magic, src);

    // PDL: wait for the zero kernel to fully complete (memory visible) only
    // NOW — all the setup above overlapped its execution + the launch gap.
    cudaGridDependencySynchronize();

    int nx  = nxcnt & 0xFF;
    int cnt = nxcnt >> 8;

    int sub = lane & (TPG - 1);
    if (sub >= cnt) return;

    int x0 = xy0 & 0xFFFF;
    int y0 = xy0 >> 16;

    for (int p = sub; p < cnt; p += TPG) {
        int oyi = (int)__umulhi((unsigned)p, (unsigned)magic);   // p / nx, exact
        int oxi = p - oyi * nx;
        int yy = y0 + oyi;
        int xx = x0 + oxi;
        float py = (float)yy - uvy;
        float px = (float)xx - uvx;
        float q = iA * px * px + 2.f * iB * px * py + iC * py * py;
        // g > 0.001  <=>  q < 2*ln(1000). Inside: expo in (-6.91, 0] so the
        // reference clamps to [-10, 0] are identity.
        if (q < 13.815511f) {
            float gg = __expf(-0.5f * q);
            float* pix = img + ((size_t)yy * WW + xx) * 3;
            atomicAdd(pix + 0, gg * w0);
            atomicAdd(pix + 1, gg * w1);
            atomicAdd(pix + 2, gg * w2);
        }
    }
}

extern "C" void kernel_launch(void* const* d_in, const int* in_sizes, int n_in,
                              void* d_out, int out_size) {
    const float* poses      = (const float*)d_in[0];
    const float* intr       = (const float*)d_in[1];
    const float* means      = (const float*)d_in[2];
    const float* log_scales = (const float*)d_in[3];
    const float4* quats     = (const float4*)d_in[4];
    const float* shs        = (const float*)d_in[5];
    const float* opac       = (const float*)d_in[6];
    float* out = (float*)d_out;

    zero_out_kernel<<<ZBLK, 256>>>((float4*)out);

    // fused kernel with programmatic dependent launch: it may start executing
    // its setup phase before zero_out_kernel completes; the in-kernel
    // cudaGridDependencySynchronize() enforces ordering for the splat writes.
    cudaLaunchConfig_t cfg = {};
    cfg.gridDim  = dim3(NBLK, 1, 1);
    cfg.blockDim = dim3(256, 1, 1);
    cfg.dynamicSmemBytes = 0;
    cfg.stream = 0;
    cudaLaunchAttribute attrs[1];
    attrs[0].id = cudaLaunchAttributeProgrammaticStreamSerialization;
    attrs[0].val.programmaticStreamSerializationAllowed = 1;
    cfg.attrs = attrs;
    cfg.numAttrs = 1;
    cudaLaunchKernelEx(&cfg, fused_kernel,
                       poses, intr, means, log_scales, quats, shs, opac, out);
}